// round 3
// baseline (speedup 1.0000x reference)
#include <cuda_runtime.h>
#include <math.h>

// Problem constants
#define NB 4
#define NL 1024
#define ND 1024
#define NH 16
#define NDK 64

// GEMM tiling
#define TM 64
#define TN 64
#define TBK 16

// ---------------------------------------------------------------------------
// Static device scratch (allocation-free rule: __device__ globals only).
// Referenced directly from device code — no cudaGetSymbolAddress anywhere.
// ---------------------------------------------------------------------------
__device__ float g_qh[NB * NH * NL * NDK];             // 16 MB  [B,H,L,DK]
__device__ float g_kh[NB * NH * NL * NDK];             // 16 MB
__device__ float g_vh[NB * NH * NL * NDK];             // 16 MB
__device__ float g_ctx[(size_t)NB * NL * ND];          // 16 MB  [B,L,H*DV]
__device__ float g_pre[(size_t)NB * NL * ND];          // 16 MB  pre-LN
__device__ float g_attn_fb[(size_t)NB * NH * NL * NL]; // 256 MB fallback attn

// ---------------------------------------------------------------------------
// Kernel 1: all three projections. blockIdx.z selects (X, W, bias, dest).
// C = X @ W^T + bias, scattered to [B,H,L,64].
// ---------------------------------------------------------------------------
__global__ __launch_bounds__(256)
void proj_kernel(const float* __restrict__ q, const float* __restrict__ k,
                 const float* __restrict__ v,
                 const float* __restrict__ w_q, const float* __restrict__ b_q,
                 const float* __restrict__ w_k, const float* __restrict__ b_k,
                 const float* __restrict__ w_v, const float* __restrict__ b_v)
{
    __shared__ float As[TBK][TM + 4];
    __shared__ float Ws[TBK][TN + 4];
    const int which = blockIdx.z;
    const float* X    = (which == 0) ? q   : (which == 1) ? k   : v;
    const float* W    = (which == 0) ? w_q : (which == 1) ? w_k : w_v;
    const float* bias = (which == 0) ? b_q : (which == 1) ? b_k : b_v;
    float* out        = (which == 0) ? g_qh : (which == 1) ? g_kh : g_vh;

    const int tid = threadIdx.x;
    const int tx = tid & 15;
    const int ty = tid >> 4;
    const int m0 = blockIdx.y * TM;
    const int n0 = blockIdx.x * TN;
    const int lr = tid >> 2;            // 0..63 tile row
    const int lc = (tid & 3) << 2;      // 0,4,8,12 k offset

    float acc[4][4] = {};
    for (int k0 = 0; k0 < ND; k0 += TBK) {
        float4 a = *(const float4*)(X + (size_t)(m0 + lr) * ND + (k0 + lc));
        float4 w = *(const float4*)(W + (size_t)(n0 + lr) * ND + (k0 + lc));
        As[lc + 0][lr] = a.x; As[lc + 1][lr] = a.y; As[lc + 2][lr] = a.z; As[lc + 3][lr] = a.w;
        Ws[lc + 0][lr] = w.x; Ws[lc + 1][lr] = w.y; Ws[lc + 2][lr] = w.z; Ws[lc + 3][lr] = w.w;
        __syncthreads();
#pragma unroll
        for (int kk = 0; kk < TBK; kk++) {
            float4 av = *(const float4*)&As[kk][ty << 2];
            float4 wv = *(const float4*)&Ws[kk][tx << 2];
            float aa[4] = {av.x, av.y, av.z, av.w};
            float ww[4] = {wv.x, wv.y, wv.z, wv.w};
#pragma unroll
            for (int i = 0; i < 4; i++)
#pragma unroll
                for (int j = 0; j < 4; j++)
                    acc[i][j] = fmaf(aa[i], ww[j], acc[i][j]);
        }
        __syncthreads();
    }
#pragma unroll
    for (int i = 0; i < 4; i++) {
        const int m = m0 + (ty << 2) + i;
        const int bb = m >> 10;
        const int l = m & (NL - 1);
#pragma unroll
        for (int j = 0; j < 4; j++) {
            const int n = n0 + (tx << 2) + j;
            const int h = n >> 6;
            const int d = n & 63;
            out[((size_t)((bb * NH + h) * NL + l)) * NDK + d] = acc[i][j] + bias[n];
        }
    }
}

// ---------------------------------------------------------------------------
// Kernel 2: scores S = (Qh Kh^T)/8 * gate, masked -> attn (pre-softmax)
// grid: (kTile=16, qTile=16, bh=64)
// ---------------------------------------------------------------------------
__global__ __launch_bounds__(256)
void scores_kernel(const float* __restrict__ gate, const int* __restrict__ mask,
                   float* __restrict__ attn_ext, int use_ext)
{
    float* attn = use_ext ? attn_ext : g_attn_fb;
    __shared__ float As[TBK][TM + 4];
    __shared__ float Ks[TBK][TN + 4];
    const int tid = threadIdx.x;
    const int tx = tid & 15;
    const int ty = tid >> 4;
    const int bh = blockIdx.z;
    const int b = bh >> 4;
    const float* Aq = g_qh + (size_t)bh * NL * NDK;
    const float* Ak = g_kh + (size_t)bh * NL * NDK;
    const int m0 = blockIdx.y * TM;
    const int n0 = blockIdx.x * TN;
    const int lr = tid >> 2;
    const int lc = (tid & 3) << 2;

    float acc[4][4] = {};
#pragma unroll
    for (int k0 = 0; k0 < NDK; k0 += TBK) {
        float4 a = *(const float4*)(Aq + (size_t)(m0 + lr) * NDK + (k0 + lc));
        float4 w = *(const float4*)(Ak + (size_t)(n0 + lr) * NDK + (k0 + lc));
        As[lc + 0][lr] = a.x; As[lc + 1][lr] = a.y; As[lc + 2][lr] = a.z; As[lc + 3][lr] = a.w;
        Ks[lc + 0][lr] = w.x; Ks[lc + 1][lr] = w.y; Ks[lc + 2][lr] = w.z; Ks[lc + 3][lr] = w.w;
        __syncthreads();
#pragma unroll
        for (int kk = 0; kk < TBK; kk++) {
            float4 av = *(const float4*)&As[kk][ty << 2];
            float4 wv = *(const float4*)&Ks[kk][tx << 2];
            float aa[4] = {av.x, av.y, av.z, av.w};
            float ww[4] = {wv.x, wv.y, wv.z, wv.w};
#pragma unroll
            for (int i = 0; i < 4; i++)
#pragma unroll
                for (int j = 0; j < 4; j++)
                    acc[i][j] = fmaf(aa[i], ww[j], acc[i][j]);
        }
        __syncthreads();
    }
#pragma unroll
    for (int i = 0; i < 4; i++) {
        const int qi = m0 + (ty << 2) + i;
#pragma unroll
        for (int j = 0; j < 4; j++) {
            const int kj = n0 + (tx << 2) + j;
            const size_t gidx = ((size_t)bh * NL + qi) * NL + kj;
            float s = acc[i][j] * 0.125f * gate[gidx];
            if (mask[((size_t)b * NL + qi) * NL + kj] > 0) s = -INFINITY;
            attn[gidx] = s;
        }
    }
}

// ---------------------------------------------------------------------------
// Kernel 3: in-place row softmax over last dim (1024). One block per row.
// ---------------------------------------------------------------------------
__global__ __launch_bounds__(256)
void softmax_kernel(float* __restrict__ attn_ext, int use_ext)
{
    float* attn = use_ext ? attn_ext : g_attn_fb;
    __shared__ float sred[8];
    __shared__ float bcast;
    const int t = threadIdx.x;
    float4* p = (float4*)(attn + (size_t)blockIdx.x * NL);
    float4 v = p[t];

    float mx = fmaxf(fmaxf(v.x, v.y), fmaxf(v.z, v.w));
#pragma unroll
    for (int o = 16; o; o >>= 1) mx = fmaxf(mx, __shfl_xor_sync(0xffffffffu, mx, o));
    if ((t & 31) == 0) sred[t >> 5] = mx;
    __syncthreads();
    if (t < 32) {
        float m2 = (t < 8) ? sred[t] : -INFINITY;
#pragma unroll
        for (int o = 4; o; o >>= 1) m2 = fmaxf(m2, __shfl_xor_sync(0xffffffffu, m2, o));
        if (t == 0) bcast = m2;
    }
    __syncthreads();
    mx = bcast;

    float4 e;
    if (mx == -INFINITY) {              // fully-masked row: define output as 0
        e.x = e.y = e.z = e.w = 0.0f;
    } else {
        e.x = expf(v.x - mx);
        e.y = expf(v.y - mx);
        e.z = expf(v.z - mx);
        e.w = expf(v.w - mx);
    }
    float s = e.x + e.y + e.z + e.w;
#pragma unroll
    for (int o = 16; o; o >>= 1) s += __shfl_xor_sync(0xffffffffu, s, o);
    __syncthreads();                    // sred reuse
    if ((t & 31) == 0) sred[t >> 5] = s;
    __syncthreads();
    if (t < 32) {
        float s2 = (t < 8) ? sred[t] : 0.0f;
#pragma unroll
        for (int o = 4; o; o >>= 1) s2 += __shfl_xor_sync(0xffffffffu, s2, o);
        if (t == 0) bcast = s2;
    }
    __syncthreads();
    const float tot = bcast;
    const float r = (tot > 0.0f) ? 1.0f / tot : 0.0f;
    e.x *= r; e.y *= r; e.z *= r; e.w *= r;
    p[t] = e;
}

// ---------------------------------------------------------------------------
// Kernel 4: ctx = attn @ Vh   per (b,h): [1024,1024]@[1024,64]
// grid: (qTile=16, bh=64); output scattered to [B,L,H*DV]
// ---------------------------------------------------------------------------
__global__ __launch_bounds__(256)
void pv_kernel(const float* __restrict__ attn_ext, int use_ext)
{
    const float* attn = use_ext ? attn_ext : g_attn_fb;
    __shared__ float As[TBK][TM + 4];
    __shared__ float Vs[TBK][TN + 4];
    const int tid = threadIdx.x;
    const int tx = tid & 15;
    const int ty = tid >> 4;
    const int m0 = blockIdx.x * TM;
    const int bh = blockIdx.y;
    const int b = bh >> 4;
    const int h = bh & 15;
    const float* Ap = attn + (size_t)bh * NL * NL;
    const float* Vp = g_vh + (size_t)bh * NL * NDK;
    const int lr = tid >> 2;
    const int lc = (tid & 3) << 2;
    const int vk = tid >> 4;            // 0..15 k-row of V tile
    const int vn = (tid & 15) << 2;     // 0..60 d col

    float acc[4][4] = {};
    for (int k0 = 0; k0 < NL; k0 += TBK) {
        float4 a = *(const float4*)(Ap + (size_t)(m0 + lr) * NL + (k0 + lc));
        As[lc + 0][lr] = a.x; As[lc + 1][lr] = a.y; As[lc + 2][lr] = a.z; As[lc + 3][lr] = a.w;
        float4 vv = *(const float4*)(Vp + (size_t)(k0 + vk) * NDK + vn);
        *(float4*)&Vs[vk][vn] = vv;
        __syncthreads();
#pragma unroll
        for (int kk = 0; kk < TBK; kk++) {
            float4 av = *(const float4*)&As[kk][ty << 2];
            float4 wv = *(const float4*)&Vs[kk][tx << 2];
            float aa[4] = {av.x, av.y, av.z, av.w};
            float ww[4] = {wv.x, wv.y, wv.z, wv.w};
#pragma unroll
            for (int i = 0; i < 4; i++)
#pragma unroll
                for (int j = 0; j < 4; j++)
                    acc[i][j] = fmaf(aa[i], ww[j], acc[i][j]);
        }
        __syncthreads();
    }
#pragma unroll
    for (int i = 0; i < 4; i++) {
        const int qi = m0 + (ty << 2) + i;
#pragma unroll
        for (int j = 0; j < 4; j++) {
            const int d = (tx << 2) + j;
            g_ctx[((size_t)(b * NL + qi)) * ND + h * NDK + d] = acc[i][j];
        }
    }
}

// ---------------------------------------------------------------------------
// Kernel 5: FC GEMM + bias + residual -> g_pre.  C = g_ctx @ W^T
// ---------------------------------------------------------------------------
__global__ __launch_bounds__(256)
void fc_kernel(const float* __restrict__ W, const float* __restrict__ bias,
               const float* __restrict__ resid)
{
    __shared__ float As[TBK][TM + 4];
    __shared__ float Ws[TBK][TN + 4];
    const int tid = threadIdx.x;
    const int tx = tid & 15;
    const int ty = tid >> 4;
    const int m0 = blockIdx.y * TM;
    const int n0 = blockIdx.x * TN;
    const int lr = tid >> 2;
    const int lc = (tid & 3) << 2;

    float acc[4][4] = {};
    for (int k0 = 0; k0 < ND; k0 += TBK) {
        float4 a = *(const float4*)(g_ctx + (size_t)(m0 + lr) * ND + (k0 + lc));
        float4 w = *(const float4*)(W + (size_t)(n0 + lr) * ND + (k0 + lc));
        As[lc + 0][lr] = a.x; As[lc + 1][lr] = a.y; As[lc + 2][lr] = a.z; As[lc + 3][lr] = a.w;
        Ws[lc + 0][lr] = w.x; Ws[lc + 1][lr] = w.y; Ws[lc + 2][lr] = w.z; Ws[lc + 3][lr] = w.w;
        __syncthreads();
#pragma unroll
        for (int kk = 0; kk < TBK; kk++) {
            float4 av = *(const float4*)&As[kk][ty << 2];
            float4 wv = *(const float4*)&Ws[kk][tx << 2];
            float aa[4] = {av.x, av.y, av.z, av.w};
            float ww[4] = {wv.x, wv.y, wv.z, wv.w};
#pragma unroll
            for (int i = 0; i < 4; i++)
#pragma unroll
                for (int j = 0; j < 4; j++)
                    acc[i][j] = fmaf(aa[i], ww[j], acc[i][j]);
        }
        __syncthreads();
    }
#pragma unroll
    for (int i = 0; i < 4; i++) {
        const int m = m0 + (ty << 2) + i;
#pragma unroll
        for (int j = 0; j < 4; j++) {
            const int n = n0 + (tx << 2) + j;
            g_pre[(size_t)m * ND + n] = acc[i][j] + bias[n] + resid[(size_t)m * ND + n];
        }
    }
}

// ---------------------------------------------------------------------------
// Kernel 6: LayerNorm over d_model, one block per row of g_pre -> d_out
// ---------------------------------------------------------------------------
__global__ __launch_bounds__(256)
void ln_kernel(const float* __restrict__ g, const float* __restrict__ beta,
               float* __restrict__ out)
{
    __shared__ float sred[8];
    __shared__ float sred2[8];
    __shared__ float bmu, brstd;
    const int t = threadIdx.x;
    const size_t row = blockIdx.x;
    const float4* p = (const float4*)(g_pre + row * ND);
    float4 v = p[t];

    float s = v.x + v.y + v.z + v.w;
    float sq = v.x * v.x + v.y * v.y + v.z * v.z + v.w * v.w;
#pragma unroll
    for (int o = 16; o; o >>= 1) {
        s += __shfl_xor_sync(0xffffffffu, s, o);
        sq += __shfl_xor_sync(0xffffffffu, sq, o);
    }
    if ((t & 31) == 0) { sred[t >> 5] = s; sred2[t >> 5] = sq; }
    __syncthreads();
    if (t < 32) {
        float s2 = (t < 8) ? sred[t] : 0.0f;
        float q2 = (t < 8) ? sred2[t] : 0.0f;
#pragma unroll
        for (int o = 4; o; o >>= 1) {
            s2 += __shfl_xor_sync(0xffffffffu, s2, o);
            q2 += __shfl_xor_sync(0xffffffffu, q2, o);
        }
        if (t == 0) {
            const float mu = s2 * (1.0f / ND);
            const float var = q2 * (1.0f / ND) - mu * mu;
            bmu = mu;
            brstd = rsqrtf(var + 1e-5f);
        }
    }
    __syncthreads();
    const float mu = bmu, rstd = brstd;
    float4 gg = ((const float4*)g)[t];
    float4 bb = ((const float4*)beta)[t];
    float4 o4;
    o4.x = (v.x - mu) * rstd * gg.x + bb.x;
    o4.y = (v.y - mu) * rstd * gg.y + bb.y;
    o4.z = (v.z - mu) * rstd * gg.z + bb.z;
    o4.w = (v.w - mu) * rstd * gg.w + bb.w;
    ((float4*)(out + row * ND))[t] = o4;
}

// ---------------------------------------------------------------------------
// Launcher — kernel launches ONLY (maximally graph-capture-safe)
// ---------------------------------------------------------------------------
extern "C" void kernel_launch(void* const* d_in, const int* in_sizes, int n_in,
                              void* d_out, int out_size)
{
    const float* q    = (const float*)d_in[0];
    const float* k    = (const float*)d_in[1];
    const float* v    = (const float*)d_in[2];
    const int*   mask = (const int*)  d_in[3];
    const float* gate = (const float*)d_in[4];
    const float* w_q  = (const float*)d_in[5];
    const float* b_q  = (const float*)d_in[6];
    const float* w_k  = (const float*)d_in[7];
    const float* b_k  = (const float*)d_in[8];
    const float* w_v  = (const float*)d_in[9];
    const float* b_v  = (const float*)d_in[10];
    const float* w_fc = (const float*)d_in[11];
    const float* b_fc = (const float*)d_in[12];
    const float* ln_g = (const float*)d_in[13];
    const float* ln_b = (const float*)d_in[14];

    const long long OUTN = 4LL * 1024 * 1024;        // 4,194,304 (out)
    const long long ATTN = 64LL * 1024 * 1024;       // 67,108,864 (attn)
    const int use_ext = ((long long)out_size >= OUTN + ATTN) ? 1 : 0;
    float* attn_ext = (float*)d_out + OUTN;          // valid only if use_ext

    // 1) Q/K/V projections -> g_qh/g_kh/g_vh  [B,H,L,DK]
    proj_kernel<<<dim3(16, 64, 3), 256>>>(q, k, v, w_q, b_q, w_k, b_k, w_v, b_v);
    // 2) scores (scaled, gated, masked) -> attn (pre-softmax)
    scores_kernel<<<dim3(16, 16, 64), 256>>>(gate, mask, attn_ext, use_ext);
    // 3) softmax in place
    softmax_kernel<<<65536, 256>>>(attn_ext, use_ext);
    // 4) P @ V -> g_ctx [B,L,H*DV]
    pv_kernel<<<dim3(16, 64), 256>>>(attn_ext, use_ext);
    // 5) FC + bias + residual -> g_pre
    fc_kernel<<<dim3(16, 64), 256>>>(w_fc, b_fc, q);
    // 6) LayerNorm -> d_out[0 : 4M]
    ln_kernel<<<4096, 256>>>(ln_g, ln_b, (float*)d_out);
}

// round 4
// speedup vs baseline: 1.8158x; 1.8158x over previous
#include <cuda_runtime.h>
#include <math.h>
#include <stdint.h>

// Problem constants
#define NB 4
#define NL 1024
#define ND 1024
#define NH 16
#define NDK 64

// ---------------------------------------------------------------------------
// Static device scratch (allocation-free rule: __device__ globals only).
// ---------------------------------------------------------------------------
__device__ float g_qh[NB * NH * NL * NDK];             // 16 MB  [B,H,L,DK]
__device__ float g_kh[NB * NH * NL * NDK];             // 16 MB
__device__ float g_vh[NB * NH * NL * NDK];             // 16 MB
__device__ float g_ctx[(size_t)NB * NL * ND];          // 16 MB  [B,L,H*DV]
__device__ float g_pre[(size_t)NB * NL * ND];          // 16 MB  pre-LN
__device__ float g_attn_fb[(size_t)NB * NH * NL * NL]; // 256 MB fallback attn

// ---------------------------------------------------------------------------
// TF32 helpers
// ---------------------------------------------------------------------------
__device__ __forceinline__ uint32_t f2tf32(float f) {
    uint32_t r;
    asm("cvt.rna.tf32.f32 %0, %1;" : "=r"(r) : "f"(f));
    return r;
}

__device__ __forceinline__ void mma_tf32(float d[4], const uint32_t a[4], const uint32_t b[2]) {
    asm volatile(
        "mma.sync.aligned.m16n8k8.row.col.f32.tf32.tf32.f32 "
        "{%0,%1,%2,%3}, {%4,%5,%6,%7}, {%8,%9}, {%0,%1,%2,%3};"
        : "+f"(d[0]), "+f"(d[1]), "+f"(d[2]), "+f"(d[3])
        : "r"(a[0]), "r"(a[1]), "r"(a[2]), "r"(a[3]), "r"(b[0]), "r"(b[1]));
}

// ---------------------------------------------------------------------------
// TF32 mma mainloop: C[128,128] tile of A[.,1024] @ B[.,1024]^T (both K-major).
// 256 threads = 8 warps (2 m x 4 n), warp tile 64x32, m16n8k8 frags.
// Smem: XOR-swizzled [128][32] u32; rows m and m+8 share a swizzle constant.
// ---------------------------------------------------------------------------
__device__ __forceinline__ void tf32_mainloop(
    const float* __restrict__ A, const float* __restrict__ B,
    uint32_t (*As)[32], uint32_t (*Bs)[32], float acc[4][4][4])
{
    const int tid = threadIdx.x;
    const int lane = tid & 31;
    const int wid = tid >> 5;
    const int gid = lane >> 2;          // 0..7
    const int tig = lane & 3;           // 0..3
    const int wm = (wid >> 2) * 64;     // warp m origin (0/64)
    const int wn = (wid & 3) * 32;      // warp n origin (0/32/64/96)
    const int ldrow = tid >> 3;         // 0..31
    const int ldcol = (tid & 7) * 4;    // 0..28

    for (int k0 = 0; k0 < 1024; k0 += 32) {
#pragma unroll
        for (int p = 0; p < 4; p++) {
            const int r = ldrow + p * 32;
            const int s = (r & 7) * 4;
            const int pc = ldcol ^ s;   // stays 4-aligned
            float4 av = *(const float4*)(A + (size_t)r * 1024 + k0 + ldcol);
            float4 bv = *(const float4*)(B + (size_t)r * 1024 + k0 + ldcol);
            uint4 ac = make_uint4(f2tf32(av.x), f2tf32(av.y), f2tf32(av.z), f2tf32(av.w));
            uint4 bc = make_uint4(f2tf32(bv.x), f2tf32(bv.y), f2tf32(bv.z), f2tf32(bv.w));
            *(uint4*)&As[r][pc] = ac;
            *(uint4*)&Bs[r][pc] = bc;
        }
        __syncthreads();
#pragma unroll
        for (int ks = 0; ks < 4; ks++) {
            const int kb = ks * 8;
            uint32_t af[4][4], bf[4][2];
#pragma unroll
            for (int mt = 0; mt < 4; mt++) {
                const int m = wm + mt * 16 + gid;
                const int sx = (m & 7) * 4;      // same for m and m+8
                af[mt][0] = As[m][(kb + tig) ^ sx];
                af[mt][1] = As[m + 8][(kb + tig) ^ sx];
                af[mt][2] = As[m][(kb + tig + 4) ^ sx];
                af[mt][3] = As[m + 8][(kb + tig + 4) ^ sx];
            }
#pragma unroll
            for (int nt = 0; nt < 4; nt++) {
                const int n = wn + nt * 8 + gid;
                const int sy = (n & 7) * 4;
                bf[nt][0] = Bs[n][(kb + tig) ^ sy];
                bf[nt][1] = Bs[n][(kb + tig + 4) ^ sy];
            }
#pragma unroll
            for (int mt = 0; mt < 4; mt++)
#pragma unroll
                for (int nt = 0; nt < 4; nt++)
                    mma_tf32(acc[mt][nt], af[mt], bf[nt]);
        }
        __syncthreads();
    }
}

// ---------------------------------------------------------------------------
// Kernel 1: projections via tf32 mma. blockIdx.z selects Q/K/V.
// C = X @ W^T + bias, scattered to [B,H,L,64].
// ---------------------------------------------------------------------------
__global__ __launch_bounds__(256)
void proj_mma(const float* __restrict__ q, const float* __restrict__ k,
              const float* __restrict__ v,
              const float* __restrict__ w_q, const float* __restrict__ b_q,
              const float* __restrict__ w_k, const float* __restrict__ b_k,
              const float* __restrict__ w_v, const float* __restrict__ b_v)
{
    __shared__ uint32_t As[128][32];
    __shared__ uint32_t Bs[128][32];
    const int which = blockIdx.z;
    const float* X    = (which == 0) ? q   : (which == 1) ? k   : v;
    const float* W    = (which == 0) ? w_q : (which == 1) ? w_k : w_v;
    const float* bias = (which == 0) ? b_q : (which == 1) ? b_k : b_v;
    float* out        = (which == 0) ? g_qh : (which == 1) ? g_kh : g_vh;

    const int m0 = blockIdx.y * 128;
    const int n0 = blockIdx.x * 128;

    float acc[4][4][4];
#pragma unroll
    for (int i = 0; i < 4; i++)
#pragma unroll
        for (int j = 0; j < 4; j++)
#pragma unroll
            for (int c = 0; c < 4; c++) acc[i][j][c] = 0.0f;

    tf32_mainloop(X + (size_t)m0 * 1024, W + (size_t)n0 * 1024, As, Bs, acc);

    const int lane = threadIdx.x & 31;
    const int wid = threadIdx.x >> 5;
    const int gid = lane >> 2, tig = lane & 3;
    const int wm = (wid >> 2) * 64, wn = (wid & 3) * 32;
    const int bb = m0 >> 10;                 // 128-aligned blocks never cross 1024

#pragma unroll
    for (int mt = 0; mt < 4; mt++) {
        const int m = m0 + wm + mt * 16 + gid;
        const int l0 = m & (NL - 1);
        const int l1 = (m + 8) & (NL - 1);
#pragma unroll
        for (int nt = 0; nt < 4; nt++) {
            const int n = n0 + wn + nt * 8 + tig * 2;
            const int h = n >> 6;
            const int d = n & 63;
            float2 bi = *(const float2*)(bias + n);
            float* base = out + ((size_t)((bb * NH + h) * NL)) * NDK + d;
            *(float2*)(base + (size_t)l0 * NDK) =
                make_float2(acc[mt][nt][0] + bi.x, acc[mt][nt][1] + bi.y);
            *(float2*)(base + (size_t)l1 * NDK) =
                make_float2(acc[mt][nt][2] + bi.x, acc[mt][nt][3] + bi.y);
        }
    }
}

// ---------------------------------------------------------------------------
// Kernel 5: FC via tf32 mma. g_pre = g_ctx @ W^T + bias + resid
// ---------------------------------------------------------------------------
__global__ __launch_bounds__(256)
void fc_mma(const float* __restrict__ W, const float* __restrict__ bias,
            const float* __restrict__ resid)
{
    __shared__ uint32_t As[128][32];
    __shared__ uint32_t Bs[128][32];
    const int m0 = blockIdx.y * 128;
    const int n0 = blockIdx.x * 128;

    float acc[4][4][4];
#pragma unroll
    for (int i = 0; i < 4; i++)
#pragma unroll
        for (int j = 0; j < 4; j++)
#pragma unroll
            for (int c = 0; c < 4; c++) acc[i][j][c] = 0.0f;

    tf32_mainloop(g_ctx + (size_t)m0 * 1024, W + (size_t)n0 * 1024, As, Bs, acc);

    const int lane = threadIdx.x & 31;
    const int wid = threadIdx.x >> 5;
    const int gid = lane >> 2, tig = lane & 3;
    const int wm = (wid >> 2) * 64, wn = (wid & 3) * 32;

#pragma unroll
    for (int mt = 0; mt < 4; mt++) {
        const int m = m0 + wm + mt * 16 + gid;
#pragma unroll
        for (int nt = 0; nt < 4; nt++) {
            const int n = n0 + wn + nt * 8 + tig * 2;
            float2 bi = *(const float2*)(bias + n);
            float2 r0 = *(const float2*)(resid + (size_t)m * ND + n);
            float2 r1 = *(const float2*)(resid + (size_t)(m + 8) * ND + n);
            *(float2*)(g_pre + (size_t)m * ND + n) =
                make_float2(acc[mt][nt][0] + bi.x + r0.x, acc[mt][nt][1] + bi.y + r0.y);
            *(float2*)(g_pre + (size_t)(m + 8) * ND + n) =
                make_float2(acc[mt][nt][2] + bi.x + r1.x, acc[mt][nt][3] + bi.y + r1.y);
        }
    }
}

// ---------------------------------------------------------------------------
// Kernel 2: scores S = (Qh Kh^T)/8 * gate, masked. 128x128 tile, 8x8 micro.
// grid: (kTile=8, qTile=8, bh=64), 256 threads.
// ---------------------------------------------------------------------------
__global__ __launch_bounds__(256)
void scores_kernel(const float* __restrict__ gate, const int* __restrict__ mask,
                   float* __restrict__ attn_ext, int use_ext)
{
    float* attn = use_ext ? attn_ext : g_attn_fb;
    __shared__ float As[16][132];
    __shared__ float Ks[16][132];
    const int tid = threadIdx.x;
    const int tx = tid & 15;            // n group
    const int ty = tid >> 4;            // m group
    const int bh = blockIdx.z;
    const int b = bh >> 4;
    const float* Aq = g_qh + (size_t)bh * NL * NDK;
    const float* Ak = g_kh + (size_t)bh * NL * NDK;
    const int m0 = blockIdx.y * 128;
    const int n0 = blockIdx.x * 128;
    const int lr = tid >> 2;            // 0..63
    const int lc = (tid & 3) << 2;      // 0,4,8,12

    float acc[8][8] = {};
#pragma unroll
    for (int k0 = 0; k0 < NDK; k0 += 16) {
#pragma unroll
        for (int p = 0; p < 2; p++) {
            const int r = lr + p * 64;
            float4 a = *(const float4*)(Aq + (size_t)(m0 + r) * NDK + k0 + lc);
            float4 w = *(const float4*)(Ak + (size_t)(n0 + r) * NDK + k0 + lc);
            As[lc + 0][r] = a.x; As[lc + 1][r] = a.y; As[lc + 2][r] = a.z; As[lc + 3][r] = a.w;
            Ks[lc + 0][r] = w.x; Ks[lc + 1][r] = w.y; Ks[lc + 2][r] = w.z; Ks[lc + 3][r] = w.w;
        }
        __syncthreads();
#pragma unroll
        for (int kk = 0; kk < 16; kk++) {
            float4 a0 = *(const float4*)&As[kk][ty * 8];
            float4 a1 = *(const float4*)&As[kk][ty * 8 + 4];
            float4 b0 = *(const float4*)&Ks[kk][tx * 8];
            float4 b1 = *(const float4*)&Ks[kk][tx * 8 + 4];
            float aa[8] = {a0.x, a0.y, a0.z, a0.w, a1.x, a1.y, a1.z, a1.w};
            float bbv[8] = {b0.x, b0.y, b0.z, b0.w, b1.x, b1.y, b1.z, b1.w};
#pragma unroll
            for (int i = 0; i < 8; i++)
#pragma unroll
                for (int j = 0; j < 8; j++)
                    acc[i][j] = fmaf(aa[i], bbv[j], acc[i][j]);
        }
        __syncthreads();
    }
#pragma unroll
    for (int i = 0; i < 8; i++) {
        const int qi = m0 + ty * 8 + i;
        const size_t rowg = ((size_t)bh * NL + qi) * NL;
        const size_t rowm = ((size_t)b * NL + qi) * NL;
#pragma unroll
        for (int jp = 0; jp < 2; jp++) {
            const int kj = n0 + tx * 8 + jp * 4;
            float4 gt = *(const float4*)(gate + rowg + kj);
            int4 mk = *(const int4*)(mask + rowm + kj);
            float4 o;
            o.x = (mk.x > 0) ? -INFINITY : acc[i][jp * 4 + 0] * 0.125f * gt.x;
            o.y = (mk.y > 0) ? -INFINITY : acc[i][jp * 4 + 1] * 0.125f * gt.y;
            o.z = (mk.z > 0) ? -INFINITY : acc[i][jp * 4 + 2] * 0.125f * gt.z;
            o.w = (mk.w > 0) ? -INFINITY : acc[i][jp * 4 + 3] * 0.125f * gt.w;
            *(float4*)(attn + rowg + kj) = o;
        }
    }
}

// ---------------------------------------------------------------------------
// Kernel 3: in-place row softmax over last dim (1024). One block per row.
// ---------------------------------------------------------------------------
__global__ __launch_bounds__(256)
void softmax_kernel(float* __restrict__ attn_ext, int use_ext)
{
    float* attn = use_ext ? attn_ext : g_attn_fb;
    __shared__ float sred[8];
    __shared__ float bcast;
    const int t = threadIdx.x;
    float4* p = (float4*)(attn + (size_t)blockIdx.x * NL);
    float4 v = p[t];

    float mx = fmaxf(fmaxf(v.x, v.y), fmaxf(v.z, v.w));
#pragma unroll
    for (int o = 16; o; o >>= 1) mx = fmaxf(mx, __shfl_xor_sync(0xffffffffu, mx, o));
    if ((t & 31) == 0) sred[t >> 5] = mx;
    __syncthreads();
    if (t < 32) {
        float m2 = (t < 8) ? sred[t] : -INFINITY;
#pragma unroll
        for (int o = 4; o; o >>= 1) m2 = fmaxf(m2, __shfl_xor_sync(0xffffffffu, m2, o));
        if (t == 0) bcast = m2;
    }
    __syncthreads();
    mx = bcast;

    float4 e;
    if (mx == -INFINITY) {
        e.x = e.y = e.z = e.w = 0.0f;
    } else {
        e.x = expf(v.x - mx);
        e.y = expf(v.y - mx);
        e.z = expf(v.z - mx);
        e.w = expf(v.w - mx);
    }
    float s = e.x + e.y + e.z + e.w;
#pragma unroll
    for (int o = 16; o; o >>= 1) s += __shfl_xor_sync(0xffffffffu, s, o);
    __syncthreads();
    if ((t & 31) == 0) sred[t >> 5] = s;
    __syncthreads();
    if (t < 32) {
        float s2 = (t < 8) ? sred[t] : 0.0f;
#pragma unroll
        for (int o = 4; o; o >>= 1) s2 += __shfl_xor_sync(0xffffffffu, s2, o);
        if (t == 0) bcast = s2;
    }
    __syncthreads();
    const float tot = bcast;
    const float r = (tot > 0.0f) ? 1.0f / tot : 0.0f;
    e.x *= r; e.y *= r; e.z *= r; e.w *= r;
    p[t] = e;
}

// ---------------------------------------------------------------------------
// Kernel 4: ctx = attn @ Vh per (b,h). 128x64 tile, 8x8 micro, 128 threads.
// grid: (qTile=8, bh=64)
// ---------------------------------------------------------------------------
__global__ __launch_bounds__(128)
void pv_kernel(const float* __restrict__ attn_ext, int use_ext)
{
    const float* attn = use_ext ? attn_ext : g_attn_fb;
    __shared__ float As[16][132];
    __shared__ float Vs[16][64];
    const int tid = threadIdx.x;
    const int tx = tid & 7;             // n group (8 x 8 cols = 64)
    const int ty = tid >> 3;            // m group (16 x 8 rows = 128)
    const int m0 = blockIdx.x * 128;
    const int bh = blockIdx.y;
    const int b = bh >> 4;
    const int h = bh & 15;
    const float* Ap = attn + (size_t)bh * NL * NL;
    const float* Vp = g_vh + (size_t)bh * NL * NDK;
    const int lr = tid >> 2;            // 0..31
    const int lc = (tid & 3) << 2;
    const int vr = tid >> 3;            // 0..15
    const int vc = (tid & 7) << 3;      // 0..56

    float acc[8][8] = {};
    for (int k0 = 0; k0 < NL; k0 += 16) {
#pragma unroll
        for (int p = 0; p < 4; p++) {
            const int r = lr + p * 32;
            float4 a = *(const float4*)(Ap + (size_t)(m0 + r) * NL + k0 + lc);
            As[lc + 0][r] = a.x; As[lc + 1][r] = a.y; As[lc + 2][r] = a.z; As[lc + 3][r] = a.w;
        }
        *(float4*)&Vs[vr][vc]     = *(const float4*)(Vp + (size_t)(k0 + vr) * NDK + vc);
        *(float4*)&Vs[vr][vc + 4] = *(const float4*)(Vp + (size_t)(k0 + vr) * NDK + vc + 4);
        __syncthreads();
#pragma unroll
        for (int kk = 0; kk < 16; kk++) {
            float4 a0 = *(const float4*)&As[kk][ty * 8];
            float4 a1 = *(const float4*)&As[kk][ty * 8 + 4];
            float4 b0 = *(const float4*)&Vs[kk][tx * 8];
            float4 b1 = *(const float4*)&Vs[kk][tx * 8 + 4];
            float aa[8] = {a0.x, a0.y, a0.z, a0.w, a1.x, a1.y, a1.z, a1.w};
            float vv[8] = {b0.x, b0.y, b0.z, b0.w, b1.x, b1.y, b1.z, b1.w};
#pragma unroll
            for (int i = 0; i < 8; i++)
#pragma unroll
                for (int j = 0; j < 8; j++)
                    acc[i][j] = fmaf(aa[i], vv[j], acc[i][j]);
        }
        __syncthreads();
    }
#pragma unroll
    for (int i = 0; i < 8; i++) {
        const int qi = m0 + ty * 8 + i;
        float* dst = g_ctx + ((size_t)(b * NL + qi)) * ND + h * NDK + tx * 8;
        *(float4*)dst = make_float4(acc[i][0], acc[i][1], acc[i][2], acc[i][3]);
        *(float4*)(dst + 4) = make_float4(acc[i][4], acc[i][5], acc[i][6], acc[i][7]);
    }
}

// ---------------------------------------------------------------------------
// Kernel 6: LayerNorm over d_model, one block per row of g_pre -> d_out
// ---------------------------------------------------------------------------
__global__ __launch_bounds__(256)
void ln_kernel(const float* __restrict__ g, const float* __restrict__ beta,
               float* __restrict__ out)
{
    __shared__ float sred[8];
    __shared__ float sred2[8];
    __shared__ float bmu, brstd;
    const int t = threadIdx.x;
    const size_t row = blockIdx.x;
    const float4* p = (const float4*)(g_pre + row * ND);
    float4 v = p[t];

    float s = v.x + v.y + v.z + v.w;
    float sq = v.x * v.x + v.y * v.y + v.z * v.z + v.w * v.w;
#pragma unroll
    for (int o = 16; o; o >>= 1) {
        s += __shfl_xor_sync(0xffffffffu, s, o);
        sq += __shfl_xor_sync(0xffffffffu, sq, o);
    }
    if ((t & 31) == 0) { sred[t >> 5] = s; sred2[t >> 5] = sq; }
    __syncthreads();
    if (t < 32) {
        float s2 = (t < 8) ? sred[t] : 0.0f;
        float q2 = (t < 8) ? sred2[t] : 0.0f;
#pragma unroll
        for (int o = 4; o; o >>= 1) {
            s2 += __shfl_xor_sync(0xffffffffu, s2, o);
            q2 += __shfl_xor_sync(0xffffffffu, q2, o);
        }
        if (t == 0) {
            const float mu = s2 * (1.0f / ND);
            const float var = q2 * (1.0f / ND) - mu * mu;
            bmu = mu;
            brstd = rsqrtf(var + 1e-5f);
        }
    }
    __syncthreads();
    const float mu = bmu, rstd = brstd;
    float4 gg = ((const float4*)g)[t];
    float4 bb = ((const float4*)beta)[t];
    float4 o4;
    o4.x = (v.x - mu) * rstd * gg.x + bb.x;
    o4.y = (v.y - mu) * rstd * gg.y + bb.y;
    o4.z = (v.z - mu) * rstd * gg.z + bb.z;
    o4.w = (v.w - mu) * rstd * gg.w + bb.w;
    ((float4*)(out + row * ND))[t] = o4;
}

// ---------------------------------------------------------------------------
// Launcher — kernel launches ONLY
// ---------------------------------------------------------------------------
extern "C" void kernel_launch(void* const* d_in, const int* in_sizes, int n_in,
                              void* d_out, int out_size)
{
    const float* q    = (const float*)d_in[0];
    const float* k    = (const float*)d_in[1];
    const float* v    = (const float*)d_in[2];
    const int*   mask = (const int*)  d_in[3];
    const float* gate = (const float*)d_in[4];
    const float* w_q  = (const float*)d_in[5];
    const float* b_q  = (const float*)d_in[6];
    const float* w_k  = (const float*)d_in[7];
    const float* b_k  = (const float*)d_in[8];
    const float* w_v  = (const float*)d_in[9];
    const float* b_v  = (const float*)d_in[10];
    const float* w_fc = (const float*)d_in[11];
    const float* b_fc = (const float*)d_in[12];
    const float* ln_g = (const float*)d_in[13];
    const float* ln_b = (const float*)d_in[14];

    const long long OUTN = 4LL * 1024 * 1024;        // out elements
    const long long ATTN = 64LL * 1024 * 1024;       // attn elements
    const int use_ext = ((long long)out_size >= OUTN + ATTN) ? 1 : 0;
    float* attn_ext = (float*)d_out + OUTN;

    // 1) Q/K/V projections (tf32 mma) -> g_qh/g_kh/g_vh
    proj_mma<<<dim3(8, 32, 3), 256>>>(q, k, v, w_q, b_q, w_k, b_k, w_v, b_v);
    // 2) scores (scaled, gated, masked) -> attn (pre-softmax)
    scores_kernel<<<dim3(8, 8, 64), 256>>>(gate, mask, attn_ext, use_ext);
    // 3) softmax in place
    softmax_kernel<<<65536, 256>>>(attn_ext, use_ext);
    // 4) P @ V -> g_ctx [B,L,H*DV]
    pv_kernel<<<dim3(8, 64), 128>>>(attn_ext, use_ext);
    // 5) FC (tf32 mma) + bias + residual -> g_pre
    fc_mma<<<dim3(8, 32), 256>>>(w_fc, b_fc, q);
    // 6) LayerNorm -> d_out[0 : 4M]
    ln_kernel<<<4096, 256>>>(ln_g, ln_b, (float*)d_out);
}